// round 12
// baseline (speedup 1.0000x reference)
#include <cuda_runtime.h>
#include <cuda_bf16.h>
#include <cstdint>

typedef unsigned long long ull;
typedef unsigned int u32;

#define M_STEPS 8
#define RMAX 64
#define P_MAX 524288
#define NGRID 148
#define NTHR 1024
#define NWARPS 32
#define PARTW 132            // 4 heads x 32-dim numerator + 4 denominators
#define C_SCALE (0.5f * 1.4426950408889634f)

// ---------------------------------------------------------------------------
// Device globals
// g_x: z_past in bf16; chunk index = p*4 + j, j covers dims [8j..8j+7].
// ---------------------------------------------------------------------------
__device__ __align__(128) uint4 g_x[(size_t)P_MAX * 4];   // 32 MB
__device__ float  g_qs[32];
__device__ float  g_z[32];
__device__ float  g_a[128];          // a[d*4+h] = sum_j qs[8h+j]*Wk[(8h+j)*32+d]
__device__ float  g_ctab[129 * 4];   // ctab[idx*4+h] = qs_h.(bk+rel[idx])_h
__device__ int    g_dpos;
__device__ float  g_partials[NGRID * PARTW];
__device__ int    g_tick[M_STEPS];

// ---------------------------------------------------------------------------
// helpers
// ---------------------------------------------------------------------------
__device__ __forceinline__ float bf_lo(u32 v) { return __uint_as_float(v << 16); }
__device__ __forceinline__ float bf_hi(u32 v) { return __uint_as_float(v & 0xFFFF0000u); }
__device__ __forceinline__ u32 packbf2(float lo, float hi) {
    u32 d; asm("cvt.rn.bf16x2.f32 %0, %1, %2;" : "=r"(d) : "f"(hi), "f"(lo));
    return d;
}
__device__ __forceinline__ float ex2f(float x) {
    float y; asm("ex2.approx.ftz.f32 %0, %1;" : "=f"(y) : "f"(x)); return y;
}

// ---------------------------------------------------------------------------
// pack z_past (fp32) -> bf16 chunks, zero-fill [P, PAD)
// ---------------------------------------------------------------------------
__global__ __launch_bounds__(256) void pack_kernel(
    const float* __restrict__ z_past, int P, int nchunks)
{
    int i = blockIdx.x * 256 + threadIdx.x;
    if (i >= nchunks) return;
    int p = i >> 2, j = i & 3;
    uint4 o = make_uint4(0u, 0u, 0u, 0u);
    if (p < P) {
        const float4* src = (const float4*)z_past + (size_t)p * 8 + j * 2;
        float4 A = src[0], B = src[1];
        o.x = packbf2(A.x, A.y);
        o.y = packbf2(A.z, A.w);
        o.z = packbf2(B.x, B.y);
        o.w = packbf2(B.z, B.w);
    }
    g_x[i] = o;
}

// ---------------------------------------------------------------------------
// per-step q-dependent parameters (a, ctab) from z state in smem
// ---------------------------------------------------------------------------
__device__ __forceinline__ void compute_step_params(
    int tid, int nthr, const float* sz, float* sqs,
    const float* __restrict__ Wq, const float* __restrict__ bq,
    const float* __restrict__ Wk, const float* __restrict__ bk,
    const float* __restrict__ rel)
{
    if (tid < 32) {
        float qv = bq[tid];
        #pragma unroll
        for (int j = 0; j < 32; j++) qv += Wq[tid * 32 + j] * sz[j];
        sqs[tid] = qv * C_SCALE;
        g_qs[tid] = sqs[tid];
    }
    __syncthreads();
    if (tid < 128) {
        int h = tid & 3, d = tid >> 2;
        float s = 0.f;
        #pragma unroll
        for (int j = 0; j < 8; j++) s += sqs[h * 8 + j] * Wk[(h * 8 + j) * 32 + d];
        g_a[d * 4 + h] = s;
    }
    for (int e = tid; e < 516; e += nthr) {
        int idx = e >> 2, h = e & 3;
        float s = 0.f;
        #pragma unroll
        for (int j = 0; j < 8; j++) {
            int i = h * 8 + j;
            s += sqs[i] * (bk[i] + rel[idx * 32 + i]);
        }
        g_ctab[idx * 4 + h] = s;
    }
}

// ---------------------------------------------------------------------------
// Init
// ---------------------------------------------------------------------------
__global__ __launch_bounds__(512) void init_kernel(
    const float* __restrict__ cand,
    const float* __restrict__ Wq, const float* __restrict__ bq,
    const float* __restrict__ Wk, const float* __restrict__ bk,
    const float* __restrict__ rel, const int* __restrict__ posp, int P)
{
    __shared__ float sz[32], sqs[32];
    int tid = threadIdx.x;
    if (tid < 32) { sz[tid] = cand[tid]; g_z[tid] = cand[tid]; }
    if (tid < M_STEPS) g_tick[tid] = 0;
    if (tid == 0) {
        int pos = P;
        if (posp) {
            int v = *posp;
            if (v > 0 && v < (1 << 28)) pos = v;
            else { float fv = __int_as_float(v); if (fv > 0.f && fv < 2.68e8f) pos = (int)fv; }
        }
        g_dpos = pos - P + RMAX;
    }
    __syncthreads();
    compute_step_params(tid, 512, sz, sqs, Wq, bq, Wk, bk, rel);
}

// ---------------------------------------------------------------------------
// Step: 3D lane split. lane = (pg = lane>>4, head = (lane>>2)&3, piece = lane&3).
// Each lane: partial score over its 8 dims (butterfly over piece axis),
// then accumulates w_head * x[piece slice]. 16 regs of state per lane.
// ---------------------------------------------------------------------------
__global__ __launch_bounds__(NTHR, 1) void step_kernel(
    int ngroups2, int P, int m,
    const float* __restrict__ Wo, const float* __restrict__ bo,
    const float* __restrict__ Wq, const float* __restrict__ bq,
    const float* __restrict__ Wk, const float* __restrict__ bk,
    const float* __restrict__ Wv, const float* __restrict__ bv,
    const float* __restrict__ rel,
    const float* __restrict__ coupling, const float* __restrict__ nscale,
    float* __restrict__ out_final, int out_elems)
{
    __shared__ float sctab[129 * 4];
    __shared__ float sa[128];
    __shared__ float sred[NWARPS][PARTW];
    __shared__ float sgrp[3][PARTW];
    __shared__ float red[PARTW];
    __shared__ float sout[32], sz[32], sqs[32];
    __shared__ int   sIsLast;

    int tid  = threadIdx.x;
    int lane = tid & 31;
    int wid  = tid >> 5;
    int piece = lane & 3;
    int head  = (lane >> 2) & 3;
    int pg    = lane >> 4;

    for (int i = tid; i < 516; i += NTHR) sctab[i] = g_ctab[i];
    if (tid < 128) sa[tid] = g_a[tid];
    __syncthreads();

    int dpos = g_dpos;

    float ar[8];
    #pragma unroll
    for (int j = 0; j < 8; j++) ar[j] = sa[(piece * 8 + j) * 4 + head];

    float acc[8];
    #pragma unroll
    for (int j = 0; j < 8; j++) acc[j] = 0.f;
    float l = 0.f;

    int gw = blockIdx.x * NWARPS + wid;
    int nw = NGRID * NWARPS;
    int off = pg * 4 + piece;   // chunk offset within the 2-position group

    #define PROC(d, gg) do {                                                  \
        float xx[8];                                                          \
        xx[0] = bf_lo(d.x); xx[1] = bf_hi(d.x);                               \
        xx[2] = bf_lo(d.y); xx[3] = bf_hi(d.y);                               \
        xx[4] = bf_lo(d.z); xx[5] = bf_hi(d.z);                               \
        xx[6] = bf_lo(d.w); xx[7] = bf_hi(d.w);                               \
        float s = 0.f;                                                        \
        _Pragma("unroll")                                                     \
        for (int j = 0; j < 8; j++) s += ar[j] * xx[j];                       \
        s += __shfl_xor_sync(0xffffffffu, s, 1);                              \
        s += __shfl_xor_sync(0xffffffffu, s, 2);                              \
        int posi = (gg) * 2 + pg;                                             \
        int idx = min(max(posi + dpos, 0), 128);                              \
        float w = ex2f(s + sctab[idx * 4 + head]);                            \
        w = (posi < P) ? w : 0.f;                                             \
        l += w;                                                               \
        _Pragma("unroll")                                                     \
        for (int j = 0; j < 8; j++) acc[j] += w * xx[j];                      \
    } while (0)

    // ngroups2 is a multiple of 8; process 2 groups (4 positions) per iter
    for (int g = gw * 2; g < ngroups2; g += nw * 2) {
        uint4 d0 = __ldg(g_x + (size_t)g * 8 + off);
        uint4 d1 = __ldg(g_x + (size_t)g * 8 + 8 + off);
        PROC(d0, g);
        PROC(d1, g + 1);
    }
    #undef PROC

    // reduce over pg axis
    #pragma unroll
    for (int j = 0; j < 8; j++) acc[j] += __shfl_xor_sync(0xffffffffu, acc[j], 16);
    l += __shfl_xor_sync(0xffffffffu, l, 16);

    if (lane < 16) {
        #pragma unroll
        for (int j = 0; j < 8; j++)
            sred[wid][head * 32 + piece * 8 + j] = acc[j];
        if (piece == 0) sred[wid][128 + head] = l;
    }
    __syncthreads();
    if (tid < PARTW) {
        float s = 0.f;
        #pragma unroll
        for (int wb = 0; wb < NWARPS; wb++) s += sred[wb][tid];
        g_partials[blockIdx.x * PARTW + tid] = s;
    }

    // ticket election
    __threadfence();
    if (tid == 0) {
        int prev = atomicAdd(&g_tick[m], 1);
        sIsLast = (prev == NGRID - 1);
    }
    __syncthreads();
    if (!sIsLast) return;

    // merge 148 x 132 partials, 3-way split
    {
        const int CH = 50;
        if (tid < 3 * PARTW) {
            int c = tid / PARTW, k = tid % PARTW;
            int b0 = c * CH, b1 = min(b0 + CH, NGRID);
            float s = 0.f;
            #pragma unroll 4
            for (int b = b0; b < b1; b++) s += __ldcg(&g_partials[b * PARTW + k]);
            sgrp[c][k] = s;
        }
        __syncthreads();
        if (tid < PARTW) red[tid] = sgrp[0][tid] + sgrp[1][tid] + sgrp[2][tid];
        __syncthreads();
    }

    // out_i = Wv[i,:]. (N_h / L_h) + bv_i,  h = i>>3
    if (tid < 32) {
        int h = tid >> 3;
        float invL = 1.f / red[128 + h];
        float s = 0.f;
        #pragma unroll
        for (int d = 0; d < 32; d++) s += Wv[tid * 32 + d] * red[h * 32 + d];
        sout[tid] = s * invL + bv[tid];
    }
    __syncthreads();

    if (tid < 32) {
        float mod = bo[tid];
        #pragma unroll
        for (int j = 0; j < 32; j++) mod += Wo[tid * 32 + j] * sout[j];
        float zz = g_z[tid] + coupling[m] * mod;

        // mish on re & im parts
        float sp = (zz > 20.f) ? zz : log1pf(expf(zz));
        float mm = zz * tanhf(sp);

        // LayerNorm over even/odd parity classes
        float s1 = mm, s2 = mm * mm;
        #pragma unroll
        for (int o = 2; o < 32; o <<= 1) {
            s1 += __shfl_xor_sync(0xffffffffu, s1, o);
            s2 += __shfl_xor_sync(0xffffffffu, s2, o);
        }
        float mu  = s1 * (1.f / 16.f);
        float var = s2 * (1.f / 16.f) - mu * mu;
        float ns  = 1.0f;
        if (nscale) {
            float nv = *nscale;
            if (isfinite(nv) && fabsf(nv) > 1e-6f && fabsf(nv) < 1e6f) ns = nv;
        }
        float zn = (mm - mu) / sqrtf(var + 1e-5f) * ns;
        sz[tid]  = zn;
        g_z[tid] = zn;
    }
    __syncthreads();

    compute_step_params(tid, NTHR, sz, sqs, Wq, bq, Wk, bk, rel);

    if (out_final && tid < 16) {
        if (out_elems == 16) out_final[tid] = sz[2 * tid];           // Re(z)
        else { out_final[2 * tid] = sz[2 * tid]; if (2 * tid + 1 < out_elems) out_final[2 * tid + 1] = sz[2 * tid + 1]; }
    }
}

// ---------------------------------------------------------------------------
// Launch
// ---------------------------------------------------------------------------
extern "C" void kernel_launch(void* const* d_in, const int* in_sizes, int n_in,
                              void* d_out, int out_size)
{
    int idx32[8], n32 = 0;
    int idx1k[8], n1k = 0;
    int idx1[4],  n1  = 0;
    int idxRel = -1, idxCoup = -1, idxBig = -1;
    long long bigSize = 0;
    for (int i = 0; i < n_in; i++) {
        int s = in_sizes[i];
        if (s == 32) { if (n32 < 8) idx32[n32++] = i; }
        else if (s == 1024) { if (n1k < 8) idx1k[n1k++] = i; }
        else if (s == 4128) idxRel = i;
        else if (s == 8) idxCoup = i;
        else if (s == 1) { if (n1 < 4) idx1[n1++] = i; }
        else if ((long long)s > bigSize) { bigSize = s; idxBig = i; }
    }
    if (idxBig < 0 || idxRel < 0 || idxCoup < 0 || n32 < 5 || n1k < 4) return;

    const float *cand, *Wq, *bq, *Wk, *bk, *Wv, *bv, *Wo, *bo;
    bool insertion = idx32[0] < idx1k[0];
    if (insertion) {
        cand = (const float*)d_in[idx32[0]];
        bq   = (const float*)d_in[idx32[1]];
        bk   = (const float*)d_in[idx32[2]];
        bv   = (const float*)d_in[idx32[3]];
        bo   = (const float*)d_in[idx32[4]];
        Wq   = (const float*)d_in[idx1k[0]];
        Wk   = (const float*)d_in[idx1k[1]];
        Wv   = (const float*)d_in[idx1k[2]];
        Wo   = (const float*)d_in[idx1k[3]];
    } else {
        Wk   = (const float*)d_in[idx1k[0]];
        Wo   = (const float*)d_in[idx1k[1]];
        Wq   = (const float*)d_in[idx1k[2]];
        Wv   = (const float*)d_in[idx1k[3]];
        bk   = (const float*)d_in[idx32[0]];
        bo   = (const float*)d_in[idx32[1]];
        bq   = (const float*)d_in[idx32[2]];
        bv   = (const float*)d_in[idx32[3]];
        cand = (const float*)d_in[idx32[4]];
    }
    const float* rel  = (const float*)d_in[idxRel];
    const float* coup = (const float*)d_in[idxCoup];
    const float* nsc  = (n1 > 0) ? (const float*)d_in[idx1[0]] : nullptr;
    const int*   pos  = (n1 > 1) ? (const int*)d_in[idx1[1]] : nullptr;

    int P = in_sizes[idxBig] / 32;
    if (P > P_MAX) P = P_MAX;
    int PAD = (P + 15) & ~15;
    int ngroups2 = PAD / 2;       // groups of 2 positions, multiple of 8
    int nchunks = PAD * 4;

    pack_kernel<<<(nchunks + 255) / 256, 256>>>((const float*)d_in[idxBig], P, nchunks);
    init_kernel<<<1, 512>>>(cand, Wq, bq, Wk, bk, rel, pos, P);

    for (int m = 0; m < M_STEPS; m++) {
        step_kernel<<<NGRID, NTHR>>>(ngroups2, P, m,
                                     Wo, bo, Wq, bq, Wk, bk, Wv, bv, rel,
                                     coup, nsc,
                                     (m == M_STEPS - 1) ? (float*)d_out : nullptr,
                                     out_size);
    }
}

// round 14
// speedup vs baseline: 1.0681x; 1.0681x over previous
#include <cuda_runtime.h>
#include <cuda_bf16.h>
#include <cstdint>

typedef unsigned long long ull;
typedef unsigned int u32;

#define M_STEPS 8
#define RMAX 64
#define P_MAX 524288
#define NB 444               // 3 blocks/SM x 148
#define NTHR 256
#define NWARPS 8
#define PARTW 132            // 4 heads x 32-dim numerator + 4 denominators
#define C_SCALE (0.5f * 1.4426950408889634f)

// ---------------------------------------------------------------------------
// Device globals
// g_x: z_past in bf16; chunk index = p*4 + j, j covers dims [8j..8j+7].
// ---------------------------------------------------------------------------
__device__ __align__(128) uint4 g_x[(size_t)P_MAX * 4];   // 32 MB
__device__ float  g_z[32];
__device__ float  g_a[128];           // a[d*4+h] = sum_j qs[8h+j]*Wk[(8h+j)*32+d]
__device__ u32    g_a2[64];           // bf16x2-packed a: [h*16 + jj*4 + piece]
__device__ float  g_ctab[130 * 4];    // [idx*4+h]; idx 129 = -1e4 sentinel
__device__ int    g_dpos;
__device__ __align__(16) float g_partials[NB * PARTW];
__device__ int    g_tick[M_STEPS];

// ---------------------------------------------------------------------------
// helpers
// ---------------------------------------------------------------------------
__device__ __forceinline__ float bf_lo(u32 v) { return __uint_as_float(v << 16); }
__device__ __forceinline__ float bf_hi(u32 v) { return __uint_as_float(v & 0xFFFF0000u); }
__device__ __forceinline__ u32 packbf2(float lo, float hi) {
    u32 d; asm("cvt.rn.bf16x2.f32 %0, %1, %2;" : "=r"(d) : "f"(hi), "f"(lo));
    return d;
}
__device__ __forceinline__ u32 hfma2bf(u32 a, u32 b, u32 c) {
    u32 d; asm("fma.rn.bf16x2 %0, %1, %2, %3;" : "=r"(d) : "r"(a), "r"(b), "r"(c));
    return d;
}
__device__ __forceinline__ ull fma2(ull a, ull b, ull c) {
    ull d; asm("fma.rn.f32x2 %0, %1, %2, %3;" : "=l"(d) : "l"(a), "l"(b), "l"(c));
    return d;
}
__device__ __forceinline__ ull pk64(u32 lo, u32 hi) {
    ull r; asm("mov.b64 %0, {%1, %2};" : "=l"(r) : "r"(lo), "r"(hi));
    return r;
}
__device__ __forceinline__ void upk64(ull v, float& lo, float& hi) {
    asm("mov.b64 {%0, %1}, %2;" : "=f"(lo), "=f"(hi) : "l"(v));
}
__device__ __forceinline__ float ex2f(float x) {
    float y; asm("ex2.approx.ftz.f32 %0, %1;" : "=f"(y) : "f"(x)); return y;
}

// ---------------------------------------------------------------------------
// pack z_past (fp32) -> bf16 chunks, zero-fill [P, PAD)
// ---------------------------------------------------------------------------
__global__ __launch_bounds__(256) void pack_kernel(
    const float* __restrict__ z_past, int P, int nchunks)
{
    int i = blockIdx.x * 256 + threadIdx.x;
    if (i >= nchunks) return;
    int p = i >> 2, j = i & 3;
    uint4 o = make_uint4(0u, 0u, 0u, 0u);
    if (p < P) {
        const float4* src = (const float4*)z_past + (size_t)p * 8 + j * 2;
        float4 A = src[0], B = src[1];
        o.x = packbf2(A.x, A.y);
        o.y = packbf2(A.z, A.w);
        o.z = packbf2(B.x, B.y);
        o.w = packbf2(B.z, B.w);
    }
    g_x[i] = o;
}

// ---------------------------------------------------------------------------
// per-step q-dependent parameters (a, a2, ctab) from z state in smem
// ---------------------------------------------------------------------------
__device__ __forceinline__ void compute_step_params(
    int tid, const float* sz, float* sqs,
    const float* __restrict__ Wq, const float* __restrict__ bq,
    const float* __restrict__ Wk, const float* __restrict__ bk,
    const float* __restrict__ rel)
{
    if (tid < 32) {
        float qv = bq[tid];
        #pragma unroll
        for (int j = 0; j < 32; j++) qv += Wq[tid * 32 + j] * sz[j];
        sqs[tid] = qv * C_SCALE;
    }
    __syncthreads();
    if (tid < 128) {
        int h = tid & 3, d = tid >> 2;
        float s = 0.f;
        #pragma unroll
        for (int j = 0; j < 8; j++) s += sqs[h * 8 + j] * Wk[(h * 8 + j) * 32 + d];
        g_a[d * 4 + h] = s;
    }
    // ctab: 129 real rows + sentinel row 129 (-1e4 -> w = 0)
    for (int e = tid; e < 520; e += NTHR) {
        int idx = e >> 2, h = e & 3;
        float s = -1e4f;
        if (idx < 129) {
            s = 0.f;
            #pragma unroll
            for (int j = 0; j < 8; j++) {
                int i = h * 8 + j;
                s += sqs[i] * (bk[i] + rel[idx * 32 + i]);
            }
        }
        g_ctab[idx * 4 + h] = s;
    }
    __syncthreads();
    if (tid < 64) {
        int h = tid >> 4, jj = (tid >> 2) & 3, pc = tid & 3;
        int d0 = pc * 8 + jj * 2;
        g_a2[tid] = packbf2(g_a[d0 * 4 + h], g_a[(d0 + 1) * 4 + h]);
    }
}

// ---------------------------------------------------------------------------
// Init
// ---------------------------------------------------------------------------
__global__ __launch_bounds__(NTHR) void init_kernel(
    const float* __restrict__ cand,
    const float* __restrict__ Wq, const float* __restrict__ bq,
    const float* __restrict__ Wk, const float* __restrict__ bk,
    const float* __restrict__ rel, const int* __restrict__ posp, int P)
{
    __shared__ float sz[32], sqs[32];
    int tid = threadIdx.x;
    if (tid < 32) { sz[tid] = cand[tid]; g_z[tid] = cand[tid]; }
    if (tid < M_STEPS) g_tick[tid] = 0;
    if (tid == 0) {
        int pos = P;
        if (posp) {
            int v = *posp;
            if (v > 0 && v < (1 << 28)) pos = v;
            else { float fv = __int_as_float(v); if (fv > 0.f && fv < 2.68e8f) pos = (int)fv; }
        }
        g_dpos = pos - P + RMAX;
    }
    __syncthreads();
    compute_step_params(tid, sz, sqs, Wq, bq, Wk, bk, rel);
}

// ---------------------------------------------------------------------------
// Step: lane = (pg = lane>>2 in 0..7 positions, piece = lane&3). Chunk index
// == lane -> 512B coalesced LDG. Per lane: 4-head partial dots via HFMA2,
// 2 shfl rounds over piece axis, fp32x2 numerator accumulation.
// ---------------------------------------------------------------------------
__global__ __launch_bounds__(NTHR, 3) void step_kernel(
    int ntiles8, int P, int m,
    const float* __restrict__ Wo, const float* __restrict__ bo,
    const float* __restrict__ Wq, const float* __restrict__ bq,
    const float* __restrict__ Wk, const float* __restrict__ bk,
    const float* __restrict__ Wv, const float* __restrict__ bv,
    const float* __restrict__ rel,
    const float* __restrict__ coupling, const float* __restrict__ nscale,
    float* __restrict__ out_final, int out_elems)
{
    __shared__ float4 sctab[130];
    __shared__ u32    sa2[64];
    __shared__ float  sred[NWARPS][PARTW];
    __shared__ float4 sgrp4[7][33];
    __shared__ float  red[PARTW];
    __shared__ float  sout[32], sz[32], sqs[32];
    __shared__ int    sIsLast;

    int tid  = threadIdx.x;
    int lane = tid & 31;
    int wid  = tid >> 5;
    int piece = lane & 3;
    int pg    = lane >> 2;

    if (tid < 130) sctab[tid] = ((const float4*)g_ctab)[tid];
    if (tid < 64)  sa2[tid] = g_a2[tid];
    __syncthreads();

    int dpos = g_dpos;

    u32 a2r[16];   // [h*4+jj] for this lane's piece
    #pragma unroll
    for (int h = 0; h < 4; h++)
        #pragma unroll
        for (int jj = 0; jj < 4; jj++)
            a2r[h * 4 + jj] = sa2[h * 16 + jj * 4 + piece];

    ull accv[16];  // [h*4+jj] packed fp32 pair = dims (piece*8+2jj, +1) head h
    #pragma unroll
    for (int i = 0; i < 16; i++) accv[i] = 0ull;
    float l[4] = {0.f, 0.f, 0.f, 0.f};

    int gw = blockIdx.x * NWARPS + wid;
    int nw = NB * NWARPS;

    const uint4* p = g_x + (size_t)gw * 32 + lane;
    long long pstep = (long long)nw * 32;

    for (int t = gw; t < ntiles8; t += nw, p += pstep) {
        uint4 d = __ldg(p);

        // scores: HFMA2 chains per head over this lane's 8 dims
        float s[4];
        #pragma unroll
        for (int h = 0; h < 4; h++) {
            u32 c = hfma2bf(d.x, a2r[h * 4 + 0], 0u);
            c = hfma2bf(d.y, a2r[h * 4 + 1], c);
            c = hfma2bf(d.z, a2r[h * 4 + 2], c);
            c = hfma2bf(d.w, a2r[h * 4 + 3], c);
            s[h] = bf_lo(c) + bf_hi(c);
        }
        #pragma unroll
        for (int h = 0; h < 4; h++) s[h] += __shfl_xor_sync(0xffffffffu, s[h], 1);
        #pragma unroll
        for (int h = 0; h < 4; h++) s[h] += __shfl_xor_sync(0xffffffffu, s[h], 2);

        int posi = t * 8 + pg;
        int idx = min(max(posi + dpos, 0), 128);
        idx = (posi < P) ? idx : 129;     // sentinel -> w = 0
        float4 ct = sctab[idx];

        float w0 = ex2f(s[0] + ct.x), w1 = ex2f(s[1] + ct.y);
        float w2 = ex2f(s[2] + ct.z), w3 = ex2f(s[3] + ct.w);
        l[0] += w0; l[1] += w1; l[2] += w2; l[3] += w3;

        // packed fp32 x pairs
        ull xx0 = pk64(d.x << 16, d.x & 0xFFFF0000u);
        ull xx1 = pk64(d.y << 16, d.y & 0xFFFF0000u);
        ull xx2 = pk64(d.z << 16, d.z & 0xFFFF0000u);
        ull xx3 = pk64(d.w << 16, d.w & 0xFFFF0000u);
        ull w20 = pk64(__float_as_uint(w0), __float_as_uint(w0));
        ull w21 = pk64(__float_as_uint(w1), __float_as_uint(w1));
        ull w22 = pk64(__float_as_uint(w2), __float_as_uint(w2));
        ull w23 = pk64(__float_as_uint(w3), __float_as_uint(w3));

        accv[0]  = fma2(xx0, w20, accv[0]);
        accv[1]  = fma2(xx1, w20, accv[1]);
        accv[2]  = fma2(xx2, w20, accv[2]);
        accv[3]  = fma2(xx3, w20, accv[3]);
        accv[4]  = fma2(xx0, w21, accv[4]);
        accv[5]  = fma2(xx1, w21, accv[5]);
        accv[6]  = fma2(xx2, w21, accv[6]);
        accv[7]  = fma2(xx3, w21, accv[7]);
        accv[8]  = fma2(xx0, w22, accv[8]);
        accv[9]  = fma2(xx1, w22, accv[9]);
        accv[10] = fma2(xx2, w22, accv[10]);
        accv[11] = fma2(xx3, w22, accv[11]);
        accv[12] = fma2(xx0, w23, accv[12]);
        accv[13] = fma2(xx1, w23, accv[13]);
        accv[14] = fma2(xx2, w23, accv[14]);
        accv[15] = fma2(xx3, w23, accv[15]);
    }

    // unpack accumulators and reduce over pg axis (lane bits 2,3,4)
    float f[32];
    #pragma unroll
    for (int i = 0; i < 16; i++) upk64(accv[i], f[2 * i], f[2 * i + 1]);
    #pragma unroll
    for (int off = 4; off <= 16; off <<= 1) {
        #pragma unroll
        for (int i = 0; i < 32; i++) f[i] += __shfl_xor_sync(0xffffffffu, f[i], off);
        #pragma unroll
        for (int h = 0; h < 4; h++) l[h] += __shfl_xor_sync(0xffffffffu, l[h], off);
    }
    // lanes 0..3 (pg==0) hold piece = lane sums; each position counted once
    if (lane < 4) {
        #pragma unroll
        for (int h = 0; h < 4; h++)
            #pragma unroll
            for (int k = 0; k < 8; k++)
                sred[wid][h * 32 + lane * 8 + k] = f[h * 8 + k];
        if (lane == 0) {
            #pragma unroll
            for (int h = 0; h < 4; h++) sred[wid][128 + h] = l[h];
        }
    }
    __syncthreads();
    if (tid < PARTW) {
        float s = 0.f;
        #pragma unroll
        for (int wb = 0; wb < NWARPS; wb++) s += sred[wb][tid];
        g_partials[blockIdx.x * PARTW + tid] = s;
    }

    // ticket election
    __threadfence();
    if (tid == 0) {
        int prev = atomicAdd(&g_tick[m], 1);
        sIsLast = (prev == NB - 1);
    }
    __syncthreads();
    if (!sIsLast) return;

    // merge NB x 132 partials: float4 columns (33), 7-way split (231 threads)
    {
        const float4* gp4 = (const float4*)g_partials;   // NB rows x 33
        const int CH = (NB + 6) / 7;                     // 64
        if (tid < 231) {
            int grp = tid / 33, c = tid % 33;
            int b0 = grp * CH, b1 = min(b0 + CH, NB);
            float4 s = make_float4(0.f, 0.f, 0.f, 0.f);
            #pragma unroll 4
            for (int b = b0; b < b1; b++) {
                float4 v = __ldcg(&gp4[b * 33 + c]);
                s.x += v.x; s.y += v.y; s.z += v.z; s.w += v.w;
            }
            sgrp4[grp][c] = s;
        }
        __syncthreads();
        if (tid < 33) {
            float4 s = make_float4(0.f, 0.f, 0.f, 0.f);
            #pragma unroll
            for (int g = 0; g < 7; g++) {
                float4 v = sgrp4[g][tid];
                s.x += v.x; s.y += v.y; s.z += v.z; s.w += v.w;
            }
            red[tid * 4 + 0] = s.x; red[tid * 4 + 1] = s.y;
            red[tid * 4 + 2] = s.z; red[tid * 4 + 3] = s.w;
        }
        __syncthreads();
    }

    // out_i = Wv[i,:].(N_h/L_h) + bv_i,  h = i>>3
    if (tid < 32) {
        int h = tid >> 3;
        float invL = 1.f / red[128 + h];
        float s = 0.f;
        #pragma unroll
        for (int d = 0; d < 32; d++) s += Wv[tid * 32 + d] * red[h * 32 + d];
        sout[tid] = s * invL + bv[tid];
    }
    __syncthreads();

    if (tid < 32) {
        float mod = bo[tid];
        #pragma unroll
        for (int j = 0; j < 32; j++) mod += Wo[tid * 32 + j] * sout[j];
        float zz = g_z[tid] + coupling[m] * mod;

        // mish on re & im parts
        float sp = (zz > 20.f) ? zz : log1pf(expf(zz));
        float mm = zz * tanhf(sp);

        // LayerNorm over even/odd parity classes
        float s1 = mm, s2 = mm * mm;
        #pragma unroll
        for (int o = 2; o < 32; o <<= 1) {
            s1 += __shfl_xor_sync(0xffffffffu, s1, o);
            s2 += __shfl_xor_sync(0xffffffffu, s2, o);
        }
        float mu  = s1 * (1.f / 16.f);
        float var = s2 * (1.f / 16.f) - mu * mu;
        float ns  = 1.0f;
        if (nscale) {
            float nv = *nscale;
            if (isfinite(nv) && fabsf(nv) > 1e-6f && fabsf(nv) < 1e6f) ns = nv;
        }
        float zn = (mm - mu) / sqrtf(var + 1e-5f) * ns;
        sz[tid]  = zn;
        g_z[tid] = zn;
    }
    __syncthreads();

    compute_step_params(tid, sz, sqs, Wq, bq, Wk, bk, rel);

    if (out_final && tid < 16) {
        if (out_elems == 16) out_final[tid] = sz[2 * tid];           // Re(z)
        else { out_final[2 * tid] = sz[2 * tid]; if (2 * tid + 1 < out_elems) out_final[2 * tid + 1] = sz[2 * tid + 1]; }
    }
}

// ---------------------------------------------------------------------------
// Launch
// ---------------------------------------------------------------------------
extern "C" void kernel_launch(void* const* d_in, const int* in_sizes, int n_in,
                              void* d_out, int out_size)
{
    int idx32[8], n32 = 0;
    int idx1k[8], n1k = 0;
    int idx1[4],  n1  = 0;
    int idxRel = -1, idxCoup = -1, idxBig = -1;
    long long bigSize = 0;
    for (int i = 0; i < n_in; i++) {
        int s = in_sizes[i];
        if (s == 32) { if (n32 < 8) idx32[n32++] = i; }
        else if (s == 1024) { if (n1k < 8) idx1k[n1k++] = i; }
        else if (s == 4128) idxRel = i;
        else if (s == 8) idxCoup = i;
        else if (s == 1) { if (n1 < 4) idx1[n1++] = i; }
        else if ((long long)s > bigSize) { bigSize = s; idxBig = i; }
    }
    if (idxBig < 0 || idxRel < 0 || idxCoup < 0 || n32 < 5 || n1k < 4) return;

    const float *cand, *Wq, *bq, *Wk, *bk, *Wv, *bv, *Wo, *bo;
    bool insertion = idx32[0] < idx1k[0];
    if (insertion) {
        cand = (const float*)d_in[idx32[0]];
        bq   = (const float*)d_in[idx32[1]];
        bk   = (const float*)d_in[idx32[2]];
        bv   = (const float*)d_in[idx32[3]];
        bo   = (const float*)d_in[idx32[4]];
        Wq   = (const float*)d_in[idx1k[0]];
        Wk   = (const float*)d_in[idx1k[1]];
        Wv   = (const float*)d_in[idx1k[2]];
        Wo   = (const float*)d_in[idx1k[3]];
    } else {
        Wk   = (const float*)d_in[idx1k[0]];
        Wo   = (const float*)d_in[idx1k[1]];
        Wq   = (const float*)d_in[idx1k[2]];
        Wv   = (const float*)d_in[idx1k[3]];
        bk   = (const float*)d_in[idx32[0]];
        bo   = (const float*)d_in[idx32[1]];
        bq   = (const float*)d_in[idx32[2]];
        bv   = (const float*)d_in[idx32[3]];
        cand = (const float*)d_in[idx32[4]];
    }
    const float* rel  = (const float*)d_in[idxRel];
    const float* coup = (const float*)d_in[idxCoup];
    const float* nsc  = (n1 > 0) ? (const float*)d_in[idx1[0]] : nullptr;
    const int*   pos  = (n1 > 1) ? (const int*)d_in[idx1[1]] : nullptr;

    int P = in_sizes[idxBig] / 32;
    if (P > P_MAX) P = P_MAX;
    int PAD = (P + 7) & ~7;
    int ntiles8 = PAD / 8;
    int nchunks = PAD * 4;

    pack_kernel<<<(nchunks + 255) / 256, 256>>>((const float*)d_in[idxBig], P, nchunks);
    init_kernel<<<1, NTHR>>>(cand, Wq, bq, Wk, bk, rel, pos, P);

    for (int m = 0; m < M_STEPS; m++) {
        step_kernel<<<NB, NTHR>>>(ntiles8, P, m,
                                  Wo, bo, Wq, bq, Wk, bk, Wv, bv, rel,
                                  coup, nsc,
                                  (m == M_STEPS - 1) ? (float*)d_out : nullptr,
                                  out_size);
    }
}

// round 15
// speedup vs baseline: 1.2161x; 1.1386x over previous
#include <cuda_runtime.h>
#include <cuda_bf16.h>
#include <cstdint>

typedef unsigned long long ull;
typedef unsigned int u32;

#define M_STEPS 8
#define RMAX 64
#define P_MAX 524288
#define NB 296
#define C_SCALE (0.5f * 1.4426950408889634f)

// ---------------------------------------------------------------------------
// g_kev layout: per tile of 32 positions, 6 uint4 slots per position:
//   g_kev[tile*192 + j*32 + lane] : slot j of position (tile*32+lane)
//   j 0..3 = KE head j dims [8j..8j+7] (bf16, k + bk + rel)
//   j 4    = V dims 0..15  (fp8 e4m3)
//   j 5    = V dims 16..31 (fp8 e4m3)
// ---------------------------------------------------------------------------
__device__ __align__(128) uint4 g_kev[(size_t)(P_MAX / 32) * 192];   // 48 MB
__device__ float g_qs[32];
__device__ float g_z[32];
__device__ float g_partials[NB * 36];
__device__ int   g_tick[M_STEPS];

// ---------------------------------------------------------------------------
// helpers
// ---------------------------------------------------------------------------
__device__ __forceinline__ ull fma2(ull a, ull b, ull c) {
    ull d; asm("fma.rn.f32x2 %0, %1, %2, %3;" : "=l"(d) : "l"(a), "l"(b), "l"(c));
    return d;
}
__device__ __forceinline__ float2 unpack2(ull a) {
    float2 r; asm("mov.b64 {%0, %1}, %2;" : "=f"(r.x), "=f"(r.y) : "l"(a));
    return r;
}
__device__ __forceinline__ float bf_lo(u32 v) { return __uint_as_float(v << 16); }
__device__ __forceinline__ float bf_hi(u32 v) { return __uint_as_float(v & 0xFFFF0000u); }
__device__ __forceinline__ float ex2f(float x) {
    float y; asm("ex2.approx.ftz.f32 %0, %1;" : "=f"(y) : "f"(x)); return y;
}
// pack two floats -> two e4m3 (low element = 'lo')
__device__ __forceinline__ unsigned short pack_e4m3x2(float lo, float hi) {
    unsigned short r;
    asm("cvt.rn.satfinite.e4m3x2.f32 %0, %1, %2;" : "=h"(r) : "f"(hi), "f"(lo));
    return r;
}
// decode 4 packed e4m3 (one u32) -> 4 floats, byte order low->high
__device__ __forceinline__ void fp8x4_f(u32 u, float& f0, float& f1, float& f2, float& f3) {
    unsigned short lo = (unsigned short)(u & 0xFFFFu);
    unsigned short hi = (unsigned short)(u >> 16);
    u32 pa, pb;
    asm("cvt.rn.f16x2.e4m3x2 %0, %1;" : "=r"(pa) : "h"(lo));
    asm("cvt.rn.f16x2.e4m3x2 %0, %1;" : "=r"(pb) : "h"(hi));
    unsigned short a0, a1, b0, b1;
    asm("mov.b32 {%0,%1}, %2;" : "=h"(a0), "=h"(a1) : "r"(pa));
    asm("mov.b32 {%0,%1}, %2;" : "=h"(b0), "=h"(b1) : "r"(pb));
    asm("cvt.f32.f16 %0, %1;" : "=f"(f0) : "h"(a0));
    asm("cvt.f32.f16 %0, %1;" : "=f"(f1) : "h"(a1));
    asm("cvt.f32.f16 %0, %1;" : "=f"(f2) : "h"(b0));
    asm("cvt.f32.f16 %0, %1;" : "=f"(f3) : "h"(b1));
}

// ---------------------------------------------------------------------------
// Precompute (FMA2, lane = output dim, W rows in registers):
//   KE[p] = Wk x_p + bk + rel[idx(p)] (bf16),  V[p] = Wv x_p + bv (fp8)
// ---------------------------------------------------------------------------
__global__ __launch_bounds__(256) void precompute_kernel(
    const float* __restrict__ z_past,
    const float* __restrict__ Wk, const float* __restrict__ bk,
    const float* __restrict__ Wv, const float* __restrict__ bv,
    const float* __restrict__ rel, const int* __restrict__ posp,
    int P, int ntiles)
{
    extern __shared__ char dyn[];
    float* srel = (float*)dyn;                          // 129*32 f = 16512 B (rel + bk)
    float* sx   = (float*)(dyn + 16512);                // 8 warps * 1024 f = 32768 B
    uint4* sstg = (uint4*)(dyn + 16512 + 32768);        // 8 warps * 288 u4 = 36864 B

    int tid = threadIdx.x, wid = tid >> 5, lane = tid & 31;

    for (int i = tid; i < 129 * 32; i += 256) srel[i] = rel[i] + bk[i & 31];
    __syncthreads();

    ull wk2[16], wv2[16];
    const ull* Wkp = (const ull*)Wk;
    const ull* Wvp = (const ull*)Wv;
    #pragma unroll
    for (int j = 0; j < 16; j++) { wk2[j] = Wkp[lane * 16 + j]; wv2[j] = Wvp[lane * 16 + j]; }
    float bvl = bv[lane];

    int pos = P;
    if (posp) {
        int v = *posp;
        if (v > 0 && v < (1 << 28)) pos = v;
        else { float fv = __int_as_float(v); if (fv > 0.f && fv < 2.68e8f) pos = (int)fv; }
    }
    int dpos = pos - P + RMAX;

    float* mysx = sx + wid * 1024;
    uint4* myst = sstg + wid * 288;                      // row pitch 9 u4 (144 B)
    unsigned short* myst16 = (unsigned short*)myst;      // row pitch 72 ushort

    int gw = blockIdx.x * 8 + wid, nw = gridDim.x * 8;
    for (int t = gw; t < ntiles; t += nw) {
        const float4* src = (const float4*)z_past + (size_t)t * 256;
        float4* dst = (float4*)mysx;
        int vcnt = P - t * 32;
        #pragma unroll
        for (int j = 0; j < 8; j++) {
            int fi = j * 32 + lane;
            float4 val = make_float4(0.f, 0.f, 0.f, 0.f);
            if ((fi >> 3) < vcnt) val = src[fi];
            dst[fi] = val;
        }
        __syncwarp();

        #pragma unroll 1
        for (int p = 0; p < 32; p++) {
            const ull* x2 = (const ull*)mysx + p * 16;
            ull ak = 0ull, av = 0ull;
            #pragma unroll
            for (int j = 0; j < 16; j++) {
                ull xx = x2[j];
                ak = fma2(wk2[j], xx, ak);
                av = fma2(wv2[j], xx, av);
            }
            float2 fk = unpack2(ak), fv2 = unpack2(av);
            int gp = t * 32 + p;
            int idx = gp + dpos; idx = min(max(idx, 0), 2 * RMAX);
            float kk = fk.x + fk.y + srel[idx * 32 + lane];
            float vv = fv2.x + fv2.y + bvl;
            if (gp >= P) { kk = 0.f; vv = 0.f; }
            myst16[p * 72 + lane]      = __bfloat16_as_ushort(__float2bfloat16(kk));
            myst16[p * 72 + 32 + lane] = __bfloat16_as_ushort(__float2bfloat16(vv));
        }
        __syncwarp();

        // write-out: KE bf16 slots 0..3, V converted to fp8 slots 4..5
        uint4* out = g_kev + (size_t)t * 192;
        #pragma unroll
        for (int j = 0; j < 4; j++) out[j * 32 + lane] = myst[lane * 9 + j];

        const u32* vr = (const u32*)(myst + lane * 9 + 4);   // 16 u32 of V bf16 pairs
        u32 w8[8];
        #pragma unroll
        for (int k = 0; k < 8; k++) {
            unsigned short us0 = pack_e4m3x2(bf_lo(vr[2 * k]),     bf_hi(vr[2 * k]));
            unsigned short us1 = pack_e4m3x2(bf_lo(vr[2 * k + 1]), bf_hi(vr[2 * k + 1]));
            w8[k] = (u32)us0 | ((u32)us1 << 16);
        }
        out[4 * 32 + lane] = make_uint4(w8[0], w8[1], w8[2], w8[3]);
        out[5 * 32 + lane] = make_uint4(w8[4], w8[5], w8[6], w8[7]);
        __syncwarp();
    }
}

// ---------------------------------------------------------------------------
// Init: z = candidate, q0 = (Wq z + bq) * C_SCALE, zero tickets
// ---------------------------------------------------------------------------
__global__ void init_kernel(const float* __restrict__ cand,
                            const float* __restrict__ Wq,
                            const float* __restrict__ bq)
{
    __shared__ float sz[32];
    int i = threadIdx.x;   // 32 threads
    sz[i] = cand[i];
    __syncwarp();
    float q = bq[i];
    #pragma unroll
    for (int j = 0; j < 32; j++) q += Wq[i * 32 + j] * sz[j];
    g_z[i]  = sz[i];
    g_qs[i] = q * C_SCALE;
    if (i < M_STEPS) g_tick[i] = 0;
}

// ---------------------------------------------------------------------------
// Step: stream bf16 KE + fp8 V (96 B/pos). 6 batched loads, fp32 scores,
// fp32 V accumulation. Last block (ticket election) runs the finalize chain.
// ---------------------------------------------------------------------------
__global__ __launch_bounds__(256, 2) void step_kernel(
    int ntiles, int P, int m,
    const float* __restrict__ Wo, const float* __restrict__ bo,
    const float* __restrict__ Wq, const float* __restrict__ bq,
    const float* __restrict__ coupling, const float* __restrict__ nscale,
    float* __restrict__ out_final, int out_elems)
{
    __shared__ float sq[32];
    __shared__ float sred[8][36];
    __shared__ int   sIsLast;
    __shared__ float sgrp[7][36];
    __shared__ float red[36];
    __shared__ float sout[32], sz[32];

    if (threadIdx.x < 32) sq[threadIdx.x] = g_qs[threadIdx.x];
    __syncthreads();

    float qf[32];
    #pragma unroll
    for (int j = 0; j < 32; j++) qf[j] = sq[j];

    float accv[32];
    #pragma unroll
    for (int j = 0; j < 32; j++) accv[j] = 0.f;
    float l[4] = {0.f, 0.f, 0.f, 0.f};

    int lane = threadIdx.x & 31;
    int gw   = (blockIdx.x * blockDim.x + threadIdx.x) >> 5;
    int nw   = (gridDim.x * blockDim.x) >> 5;

    int tfull = P >> 5;
    int rem   = P & 31;

    // fp32 dot of one bf16x2-packed KE chunk (uint4 = 8 dims) with qf[8h..]
    #define DOT8(kc, h, sacc)                                                \
        sacc += bf_lo(kc.x) * qf[8*(h)+0]; sacc += bf_hi(kc.x) * qf[8*(h)+1];\
        sacc += bf_lo(kc.y) * qf[8*(h)+2]; sacc += bf_hi(kc.y) * qf[8*(h)+3];\
        sacc += bf_lo(kc.z) * qf[8*(h)+4]; sacc += bf_hi(kc.z) * qf[8*(h)+5];\
        sacc += bf_lo(kc.w) * qf[8*(h)+6]; sacc += bf_hi(kc.w) * qf[8*(h)+7];
    // accumulate 4 fp8 dims from u32 'uu' at dim base 'db' with weight ww
    #define ACC4(uu, db, ww) do {                                            \
        float _f0, _f1, _f2, _f3;                                            \
        fp8x4_f(uu, _f0, _f1, _f2, _f3);                                     \
        accv[(db)+0] += (ww) * _f0; accv[(db)+1] += (ww) * _f1;              \
        accv[(db)+2] += (ww) * _f2; accv[(db)+3] += (ww) * _f3;              \
    } while (0)

    for (int t = gw; t < tfull; t += nw) {
        const uint4* b = g_kev + (size_t)t * 192 + lane;
        // batch all 6 loads
        uint4 ke0 = __ldg(b);       uint4 ke1 = __ldg(b + 32);
        uint4 ke2 = __ldg(b + 64);  uint4 ke3 = __ldg(b + 96);
        uint4 v0  = __ldg(b + 128); uint4 v1  = __ldg(b + 160);

        float s0 = 0.f, s1 = 0.f, s2 = 0.f, s3 = 0.f;
        DOT8(ke0, 0, s0) DOT8(ke1, 1, s1) DOT8(ke2, 2, s2) DOT8(ke3, 3, s3)
        float w0 = ex2f(s0), w1 = ex2f(s1), w2 = ex2f(s2), w3 = ex2f(s3);
        l[0] += w0; l[1] += w1; l[2] += w2; l[3] += w3;

        ACC4(v0.x, 0,  w0); ACC4(v0.y, 4,  w0);
        ACC4(v0.z, 8,  w1); ACC4(v0.w, 12, w1);
        ACC4(v1.x, 16, w2); ACC4(v1.y, 20, w2);
        ACC4(v1.z, 24, w3); ACC4(v1.w, 28, w3);
    }

    // masked tail tile (only when P % 32 != 0)
    if (rem && gw == (tfull % nw)) {
        const uint4* b = g_kev + (size_t)tfull * 192 + lane;
        uint4 ke0 = __ldg(b);       uint4 ke1 = __ldg(b + 32);
        uint4 ke2 = __ldg(b + 64);  uint4 ke3 = __ldg(b + 96);
        uint4 v0  = __ldg(b + 128); uint4 v1  = __ldg(b + 160);
        float mask = (lane < rem) ? 1.f : 0.f;

        float s0 = 0.f, s1 = 0.f, s2 = 0.f, s3 = 0.f;
        DOT8(ke0, 0, s0) DOT8(ke1, 1, s1) DOT8(ke2, 2, s2) DOT8(ke3, 3, s3)
        float w0 = ex2f(s0) * mask, w1 = ex2f(s1) * mask;
        float w2 = ex2f(s2) * mask, w3 = ex2f(s3) * mask;
        l[0] += w0; l[1] += w1; l[2] += w2; l[3] += w3;

        ACC4(v0.x, 0,  w0); ACC4(v0.y, 4,  w0);
        ACC4(v0.z, 8,  w1); ACC4(v0.w, 12, w1);
        ACC4(v1.x, 16, w2); ACC4(v1.y, 20, w2);
        ACC4(v1.z, 24, w3); ACC4(v1.w, 28, w3);
    }
    #undef DOT8
    #undef ACC4

    // 36-value reduction: warp, then block, then per-block partial
    float vals[36];
    #pragma unroll
    for (int j = 0; j < 32; j++) vals[j] = accv[j];
    #pragma unroll
    for (int h = 0; h < 4; h++) vals[32 + h] = l[h];

    #pragma unroll
    for (int off = 16; off; off >>= 1) {
        #pragma unroll
        for (int k = 0; k < 36; k++)
            vals[k] += __shfl_xor_sync(0xffffffffu, vals[k], off);
    }
    int warp = threadIdx.x >> 5;
    if (lane == 0) {
        #pragma unroll
        for (int k = 0; k < 36; k++) sred[warp][k] = vals[k];
    }
    __syncthreads();
    if (threadIdx.x < 36) {
        float ssum = 0.f;
        #pragma unroll
        for (int wb = 0; wb < 8; wb++) ssum += sred[wb][threadIdx.x];
        g_partials[blockIdx.x * 36 + threadIdx.x] = ssum;
    }

    // ticket election: last finishing block does the finalize chain
    __threadfence();
    if (threadIdx.x == 0) {
        int prev = atomicAdd(&g_tick[m], 1);
        sIsLast = (prev == (int)gridDim.x - 1);
    }
    __syncthreads();
    if (!sIsLast) return;

    int tid = threadIdx.x;
    int nblocks = gridDim.x;
    int chunk = (nblocks + 6) / 7;
    if (tid < 252) {
        int g = tid / 36, k = tid % 36;
        int b0 = g * chunk, b1 = min(b0 + chunk, nblocks);
        float s = 0.f;
        for (int b = b0; b < b1; b++) s += __ldcg(&g_partials[b * 36 + k]);
        sgrp[g][k] = s;
    }
    __syncthreads();
    if (tid < 36) {
        float s = 0.f;
        #pragma unroll
        for (int g = 0; g < 7; g++) s += sgrp[g][tid];
        red[tid] = s;
    }
    __syncthreads();
    if (tid < 32) sout[tid] = red[tid] / red[32 + (tid >> 3)];
    __syncthreads();

    if (tid < 32) {
        float mod = bo[tid];
        #pragma unroll
        for (int j = 0; j < 32; j++) mod += Wo[tid * 32 + j] * sout[j];
        float zz = g_z[tid] + coupling[m] * mod;

        // mish on re & im parts
        float sp = (zz > 20.f) ? zz : log1pf(expf(zz));
        float mm = zz * tanhf(sp);

        // LayerNorm over even/odd parity classes
        float s1 = mm, s2 = mm * mm;
        #pragma unroll
        for (int off = 2; off < 32; off <<= 1) {
            s1 += __shfl_xor_sync(0xffffffffu, s1, off);
            s2 += __shfl_xor_sync(0xffffffffu, s2, off);
        }
        float mu  = s1 * (1.f / 16.f);
        float var = s2 * (1.f / 16.f) - mu * mu;
        float ns  = 1.0f;
        if (nscale) {
            float nv = *nscale;
            if (isfinite(nv) && fabsf(nv) > 1e-6f && fabsf(nv) < 1e6f) ns = nv;
        }
        float zn = (mm - mu) / sqrtf(var + 1e-5f) * ns;

        sz[tid]  = zn;
        g_z[tid] = zn;
    }
    __syncwarp(0xffffffffu);
    if (tid < 32) {
        float qv = bq[tid];
        #pragma unroll
        for (int j = 0; j < 32; j++) qv += Wq[tid * 32 + j] * sz[j];
        g_qs[tid] = qv * C_SCALE;
    }
    if (out_final && tid < 16) {
        if (out_elems == 16) out_final[tid] = sz[2 * tid];           // Re(z)
        else { out_final[2 * tid] = sz[2 * tid]; if (2 * tid + 1 < out_elems) out_final[2 * tid + 1] = sz[2 * tid + 1]; }
    }
}

// ---------------------------------------------------------------------------
// Launch
// ---------------------------------------------------------------------------
extern "C" void kernel_launch(void* const* d_in, const int* in_sizes, int n_in,
                              void* d_out, int out_size)
{
    int idx32[8], n32 = 0;
    int idx1k[8], n1k = 0;
    int idx1[4],  n1  = 0;
    int idxRel = -1, idxCoup = -1, idxBig = -1;
    long long bigSize = 0;
    for (int i = 0; i < n_in; i++) {
        int s = in_sizes[i];
        if (s == 32) { if (n32 < 8) idx32[n32++] = i; }
        else if (s == 1024) { if (n1k < 8) idx1k[n1k++] = i; }
        else if (s == 4128) idxRel = i;
        else if (s == 8) idxCoup = i;
        else if (s == 1) { if (n1 < 4) idx1[n1++] = i; }
        else if ((long long)s > bigSize) { bigSize = s; idxBig = i; }
    }
    if (idxBig < 0 || idxRel < 0 || idxCoup < 0 || n32 < 5 || n1k < 4) return;

    const float *cand, *Wq, *bq, *Wk, *bk, *Wv, *bv, *Wo, *bo;
    bool insertion = idx32[0] < idx1k[0];
    if (insertion) {
        cand = (const float*)d_in[idx32[0]];
        bq   = (const float*)d_in[idx32[1]];
        bk   = (const float*)d_in[idx32[2]];
        bv   = (const float*)d_in[idx32[3]];
        bo   = (const float*)d_in[idx32[4]];
        Wq   = (const float*)d_in[idx1k[0]];
        Wk   = (const float*)d_in[idx1k[1]];
        Wv   = (const float*)d_in[idx1k[2]];
        Wo   = (const float*)d_in[idx1k[3]];
    } else {
        Wk   = (const float*)d_in[idx1k[0]];
        Wo   = (const float*)d_in[idx1k[1]];
        Wq   = (const float*)d_in[idx1k[2]];
        Wv   = (const float*)d_in[idx1k[3]];
        bk   = (const float*)d_in[idx32[0]];
        bo   = (const float*)d_in[idx32[1]];
        bq   = (const float*)d_in[idx32[2]];
        bv   = (const float*)d_in[idx32[3]];
        cand = (const float*)d_in[idx32[4]];
    }
    const float* rel  = (const float*)d_in[idxRel];
    const float* coup = (const float*)d_in[idxCoup];
    const float* nsc  = (n1 > 0) ? (const float*)d_in[idx1[0]] : nullptr;
    const int*   pos  = (n1 > 1) ? (const int*)d_in[idx1[1]] : nullptr;

    int P = in_sizes[idxBig] / 32;
    if (P > P_MAX) P = P_MAX;
    int PAD = (P + 31) & ~31;
    int ntiles = PAD / 32;

    static int smem_set = 0;
    const int PRE_SMEM = 16512 + 32768 + 36864;   // 86144 B
    if (!smem_set) {
        cudaFuncSetAttribute(precompute_kernel,
                             cudaFuncAttributeMaxDynamicSharedMemorySize, PRE_SMEM);
        smem_set = 1;
    }

    precompute_kernel<<<148, 256, PRE_SMEM>>>((const float*)d_in[idxBig],
                                              Wk, bk, Wv, bv, rel, pos, P, ntiles);
    init_kernel<<<1, 32>>>(cand, Wq, bq);

    for (int m = 0; m < M_STEPS; m++) {
        step_kernel<<<NB, 256>>>(ntiles, P, m, Wo, bo, Wq, bq, coup, nsc,
                                 (m == M_STEPS - 1) ? (float*)d_out : nullptr,
                                 out_size);
    }
}

// round 17
// speedup vs baseline: 1.2216x; 1.0046x over previous
#include <cuda_runtime.h>
#include <cuda_bf16.h>
#include <cstdint>

typedef unsigned long long ull;
typedef unsigned int u32;
typedef unsigned short u16;

#define M_STEPS 8
#define RMAX 64
#define P_MAX 524288
#define NB 296
#define C_SCALE (0.5f * 1.4426950408889634f)

// ---------------------------------------------------------------------------
// g_kev layout: per tile of 32 positions, 6 uint4 slots per position:
//   g_kev[tile*192 + j*32 + lane] : slot j of position (tile*32+lane)
//   j 0..3 = KE head j dims [8j..8j+7] (bf16, k + bk + rel)
//   j 4    = V dims 0..15  (fp8 e4m3)
//   j 5    = V dims 16..31 (fp8 e4m3)
// ---------------------------------------------------------------------------
__device__ __align__(128) uint4 g_kev[(size_t)(P_MAX / 32) * 192];   // 48 MB
__device__ float g_qs[32];
__device__ float g_z[32];
__device__ float g_partials[NB * 36];
__device__ int   g_tick[M_STEPS];

// ---------------------------------------------------------------------------
// helpers
// ---------------------------------------------------------------------------
__device__ __forceinline__ ull fma2(ull a, ull b, ull c) {
    ull d; asm("fma.rn.f32x2 %0, %1, %2, %3;" : "=l"(d) : "l"(a), "l"(b), "l"(c));
    return d;
}
__device__ __forceinline__ float2 unpack2(ull a) {
    float2 r; asm("mov.b64 {%0, %1}, %2;" : "=f"(r.x), "=f"(r.y) : "l"(a));
    return r;
}
__device__ __forceinline__ float bf_lo(u32 v) { return __uint_as_float(v << 16); }
__device__ __forceinline__ float bf_hi(u32 v) { return __uint_as_float(v & 0xFFFF0000u); }
__device__ __forceinline__ float ex2f(float x) {
    float y; asm("ex2.approx.ftz.f32 %0, %1;" : "=f"(y) : "f"(x)); return y;
}
__device__ __forceinline__ u16 pack_e4m3x2(float lo, float hi) {
    u16 r;
    asm("cvt.rn.satfinite.e4m3x2.f32 %0, %1, %2;" : "=h"(r) : "f"(hi), "f"(lo));
    return r;
}
// decode 4 packed e4m3 (one u32) -> 4 floats, byte order low->high
__device__ __forceinline__ void fp8x4_f(u32 u, float& f0, float& f1, float& f2, float& f3) {
    u16 lo = (u16)(u & 0xFFFFu);
    u16 hi = (u16)(u >> 16);
    u32 pa, pb;
    asm("cvt.rn.f16x2.e4m3x2 %0, %1;" : "=r"(pa) : "h"(lo));
    asm("cvt.rn.f16x2.e4m3x2 %0, %1;" : "=r"(pb) : "h"(hi));
    u16 a0, a1, b0, b1;
    asm("mov.b32 {%0,%1}, %2;" : "=h"(a0), "=h"(a1) : "r"(pa));
    asm("mov.b32 {%0,%1}, %2;" : "=h"(b0), "=h"(b1) : "r"(pb));
    asm("cvt.f32.f16 %0, %1;" : "=f"(f0) : "h"(a0));
    asm("cvt.f32.f16 %0, %1;" : "=f"(f1) : "h"(a1));
    asm("cvt.f32.f16 %0, %1;" : "=f"(f2) : "h"(b0));
    asm("cvt.f32.f16 %0, %1;" : "=f"(f3) : "h"(b1));
}

// ---------------------------------------------------------------------------
// Precompute (FMA2, lane = output dim, W rows in registers):
//   KE[p] = Wk x_p + bk + rel[idx(p)] (bf16),  V[p] = Wv x_p + bv (fp8)
// ---------------------------------------------------------------------------
__global__ __launch_bounds__(256) void precompute_kernel(
    const float* __restrict__ z_past,
    const float* __restrict__ Wk, const float* __restrict__ bk,
    const float* __restrict__ Wv, const float* __restrict__ bv,
    const float* __restrict__ rel, const int* __restrict__ posp,
    int P, int ntiles)
{
    extern __shared__ char dyn[];
    float* srel = (float*)dyn;                          // 129*32 f = 16512 B (rel + bk)
    float* sx   = (float*)(dyn + 16512);                // 8 warps * 1024 f = 32768 B
    uint4* sstg = (uint4*)(dyn + 16512 + 32768);        // 8 warps * 288 u4 = 36864 B

    int tid = threadIdx.x, wid = tid >> 5, lane = tid & 31;

    for (int i = tid; i < 129 * 32; i += 256) srel[i] = rel[i] + bk[i & 31];
    __syncthreads();

    ull wk2[16], wv2[16];
    const ull* Wkp = (const ull*)Wk;
    const ull* Wvp = (const ull*)Wv;
    #pragma unroll
    for (int j = 0; j < 16; j++) { wk2[j] = Wkp[lane * 16 + j]; wv2[j] = Wvp[lane * 16 + j]; }
    float bvl = bv[lane];

    int pos = P;
    if (posp) {
        int v = *posp;
        if (v > 0 && v < (1 << 28)) pos = v;
        else { float fv = __int_as_float(v); if (fv > 0.f && fv < 2.68e8f) pos = (int)fv; }
    }
    int dpos = pos - P + RMAX;

    float* mysx = sx + wid * 1024;
    uint4* myst = sstg + wid * 288;                      // row pitch 9 u4 (144 B)
    unsigned short* myst16 = (unsigned short*)myst;      // row pitch 72 ushort

    int gw = blockIdx.x * 8 + wid, nw = gridDim.x * 8;
    for (int t = gw; t < ntiles; t += nw) {
        const float4* src = (const float4*)z_past + (size_t)t * 256;
        float4* dst = (float4*)mysx;
        int vcnt = P - t * 32;
        #pragma unroll
        for (int j = 0; j < 8; j++) {
            int fi = j * 32 + lane;
            float4 val = make_float4(0.f, 0.f, 0.f, 0.f);
            if ((fi >> 3) < vcnt) val = src[fi];
            dst[fi] = val;
        }
        __syncwarp();

        #pragma unroll 1
        for (int p = 0; p < 32; p++) {
            const ull* x2 = (const ull*)mysx + p * 16;
            ull ak = 0ull, av = 0ull;
            #pragma unroll
            for (int j = 0; j < 16; j++) {
                ull xx = x2[j];
                ak = fma2(wk2[j], xx, ak);
                av = fma2(wv2[j], xx, av);
            }
            float2 fk = unpack2(ak), fv2 = unpack2(av);
            int gp = t * 32 + p;
            int idx = gp + dpos; idx = min(max(idx, 0), 2 * RMAX);
            float kk = fk.x + fk.y + srel[idx * 32 + lane];
            float vv = fv2.x + fv2.y + bvl;
            if (gp >= P) { kk = 0.f; vv = 0.f; }
            myst16[p * 72 + lane]      = __bfloat16_as_ushort(__float2bfloat16(kk));
            myst16[p * 72 + 32 + lane] = __bfloat16_as_ushort(__float2bfloat16(vv));
        }
        __syncwarp();

        // write-out: KE bf16 slots 0..3, V converted to fp8 slots 4..5
        uint4* out = g_kev + (size_t)t * 192;
        #pragma unroll
        for (int j = 0; j < 4; j++) out[j * 32 + lane] = myst[lane * 9 + j];

        const u32* vr = (const u32*)(myst + lane * 9 + 4);   // 16 u32 of V bf16 pairs
        u32 w8[8];
        #pragma unroll
        for (int k = 0; k < 8; k++) {
            u16 us0 = pack_e4m3x2(bf_lo(vr[2 * k]),     bf_hi(vr[2 * k]));
            u16 us1 = pack_e4m3x2(bf_lo(vr[2 * k + 1]), bf_hi(vr[2 * k + 1]));
            w8[k] = (u32)us0 | ((u32)us1 << 16);
        }
        out[4 * 32 + lane] = make_uint4(w8[0], w8[1], w8[2], w8[3]);
        out[5 * 32 + lane] = make_uint4(w8[4], w8[5], w8[6], w8[7]);
        __syncwarp();
    }
}

// ---------------------------------------------------------------------------
// Init: z = candidate, q0 = (Wq z + bq) * C_SCALE, zero tickets
// ---------------------------------------------------------------------------
__global__ void init_kernel(const float* __restrict__ cand,
                            const float* __restrict__ Wq,
                            const float* __restrict__ bq)
{
    __shared__ float sz[32];
    int i = threadIdx.x;   // 32 threads
    sz[i] = cand[i];
    __syncwarp();
    float q = bq[i];
    #pragma unroll
    for (int j = 0; j < 32; j++) q += Wq[i * 32 + j] * sz[j];
    g_z[i]  = sz[i];
    g_qs[i] = q * C_SCALE;
    if (i < M_STEPS) g_tick[i] = 0;
}

// ---------------------------------------------------------------------------
// Step: stream bf16 KE + fp8 V (96 B/pos, 48 MB). U=2 adjacent tiles per
// iteration: 12 batched LDG.128 (6 KB in flight/warp). fp32 scores, fp32 V
// accumulation. Last block (ticket election) runs the finalize chain.
// ---------------------------------------------------------------------------
__global__ __launch_bounds__(256, 2) void step_kernel(
    int ntiles, int P, int m,
    const float* __restrict__ Wo, const float* __restrict__ bo,
    const float* __restrict__ Wq, const float* __restrict__ bq,
    const float* __restrict__ coupling, const float* __restrict__ nscale,
    float* __restrict__ out_final, int out_elems)
{
    __shared__ float sq[32];
    __shared__ float sred[8][36];
    __shared__ int   sIsLast;
    __shared__ float sgrp[7][36];
    __shared__ float red[36];
    __shared__ float sout[32], sz[32];

    if (threadIdx.x < 32) sq[threadIdx.x] = g_qs[threadIdx.x];
    __syncthreads();

    float qf[32];
    #pragma unroll
    for (int j = 0; j < 32; j++) qf[j] = sq[j];

    float accv[32];
    #pragma unroll
    for (int j = 0; j < 32; j++) accv[j] = 0.f;
    float l[4] = {0.f, 0.f, 0.f, 0.f};

    int lane = threadIdx.x & 31;
    int gw   = (blockIdx.x * blockDim.x + threadIdx.x) >> 5;
    int nw   = (gridDim.x * blockDim.x) >> 5;

    // fp32 dot of one bf16x2-packed KE chunk (uint4 = 8 dims) with qf[8h..]
    #define DOT8(kc, h, sacc)                                                \
        sacc += bf_lo(kc.x) * qf[8*(h)+0]; sacc += bf_hi(kc.x) * qf[8*(h)+1];\
        sacc += bf_lo(kc.y) * qf[8*(h)+2]; sacc += bf_hi(kc.y) * qf[8*(h)+3];\
        sacc += bf_lo(kc.z) * qf[8*(h)+4]; sacc += bf_hi(kc.z) * qf[8*(h)+5];\
        sacc += bf_lo(kc.w) * qf[8*(h)+6]; sacc += bf_hi(kc.w) * qf[8*(h)+7];
    // accumulate 4 fp8 dims from u32 'uu' at dim base 'db' with weight ww
    #define ACC4(uu, db, ww) do {                                            \
        float _f0, _f1, _f2, _f3;                                            \
        fp8x4_f(uu, _f0, _f1, _f2, _f3);                                     \
        accv[(db)+0] += (ww) * _f0; accv[(db)+1] += (ww) * _f1;              \
        accv[(db)+2] += (ww) * _f2; accv[(db)+3] += (ww) * _f3;              \
    } while (0)
    #define PROC(K0, K1, K2, K3, V0, V1, tt) do {                            \
        float s0 = 0.f, s1 = 0.f, s2 = 0.f, s3 = 0.f;                        \
        DOT8(K0, 0, s0) DOT8(K1, 1, s1) DOT8(K2, 2, s2) DOT8(K3, 3, s3)      \
        float mask = ((tt) * 32 + lane < P) ? 1.f : 0.f;                     \
        float w0 = ex2f(s0) * mask, w1 = ex2f(s1) * mask;                    \
        float w2 = ex2f(s2) * mask, w3 = ex2f(s3) * mask;                    \
        l[0] += w0; l[1] += w1; l[2] += w2; l[3] += w3;                      \
        ACC4(V0.x, 0,  w0); ACC4(V0.y, 4,  w0);                              \
        ACC4(V0.z, 8,  w1); ACC4(V0.w, 12, w1);                              \
        ACC4(V1.x, 16, w2); ACC4(V1.y, 20, w2);                              \
        ACC4(V1.z, 24, w3); ACC4(V1.w, 28, w3);                              \
    } while (0)

    // ntiles is even (PAD to 64 positions); U=2 adjacent tiles per iteration
    for (int t = gw * 2; t < ntiles; t += nw * 2) {
        const uint4* b = g_kev + (size_t)t * 192 + lane;
        // tile t (6 loads) + tile t+1 (6 loads), all batched: 6 KB in flight
        uint4 A0 = __ldg(b);       uint4 A1 = __ldg(b + 32);
        uint4 A2 = __ldg(b + 64);  uint4 A3 = __ldg(b + 96);
        uint4 A4 = __ldg(b + 128); uint4 A5 = __ldg(b + 160);
        uint4 B0 = __ldg(b + 192); uint4 B1 = __ldg(b + 224);
        uint4 B2 = __ldg(b + 256); uint4 B3 = __ldg(b + 288);
        uint4 B4 = __ldg(b + 320); uint4 B5 = __ldg(b + 352);

        PROC(A0, A1, A2, A3, A4, A5, t);
        PROC(B0, B1, B2, B3, B4, B5, t + 1);
    }
    #undef PROC
    #undef DOT8
    #undef ACC4

    // 36-value reduction: warp, then block, then per-block partial
    float vals[36];
    #pragma unroll
    for (int j = 0; j < 32; j++) vals[j] = accv[j];
    #pragma unroll
    for (int h = 0; h < 4; h++) vals[32 + h] = l[h];

    #pragma unroll
    for (int off = 16; off; off >>= 1) {
        #pragma unroll
        for (int k = 0; k < 36; k++)
            vals[k] += __shfl_xor_sync(0xffffffffu, vals[k], off);
    }
    int warp = threadIdx.x >> 5;
    if (lane == 0) {
        #pragma unroll
        for (int k = 0; k < 36; k++) sred[warp][k] = vals[k];
    }
    __syncthreads();
    if (threadIdx.x < 36) {
        float ssum = 0.f;
        #pragma unroll
        for (int wb = 0; wb < 8; wb++) ssum += sred[wb][threadIdx.x];
        g_partials[blockIdx.x * 36 + threadIdx.x] = ssum;
    }

    // ticket election: last finishing block does the finalize chain
    __threadfence();
    if (threadIdx.x == 0) {
        int prev = atomicAdd(&g_tick[m], 1);
        sIsLast = (prev == (int)gridDim.x - 1);
    }
    __syncthreads();
    if (!sIsLast) return;

    int tid = threadIdx.x;
    int nblocks = gridDim.x;
    int chunk = (nblocks + 6) / 7;
    if (tid < 252) {
        int g = tid / 36, k = tid % 36;
        int b0 = g * chunk, b1 = min(b0 + chunk, nblocks);
        float s = 0.f;
        for (int b = b0; b < b1; b++) s += __ldcg(&g_partials[b * 36 + k]);
        sgrp[g][k] = s;
    }
    __syncthreads();
    if (tid < 36) {
        float s = 0.f;
        #pragma unroll
        for (int g = 0; g < 7; g++) s += sgrp[g][tid];
        red[tid] = s;
    }
    __syncthreads();
    if (tid < 32) sout[tid] = red[tid] / red[32 + (tid >> 3)];
    __syncthreads();

    if (tid < 32) {
        float mod = bo[tid];
        #pragma unroll
        for (int j = 0; j < 32; j++) mod += Wo[tid * 32 + j] * sout[j];
        float zz = g_z[tid] + coupling[m] * mod;

        // mish on re & im parts
        float sp = (zz > 20.f) ? zz : log1pf(expf(zz));
        float mm = zz * tanhf(sp);

        // LayerNorm over even/odd parity classes
        float s1 = mm, s2 = mm * mm;
        #pragma unroll
        for (int off = 2; off < 32; off <<= 1) {
            s1 += __shfl_xor_sync(0xffffffffu, s1, off);
            s2 += __shfl_xor_sync(0xffffffffu, s2, off);
        }
        float mu  = s1 * (1.f / 16.f);
        float var = s2 * (1.f / 16.f) - mu * mu;
        float ns  = 1.0f;
        if (nscale) {
            float nv = *nscale;
            if (isfinite(nv) && fabsf(nv) > 1e-6f && fabsf(nv) < 1e6f) ns = nv;
        }
        float zn = (mm - mu) / sqrtf(var + 1e-5f) * ns;

        sz[tid]  = zn;
        g_z[tid] = zn;
    }
    __syncwarp(0xffffffffu);
    if (tid < 32) {
        float qv = bq[tid];
        #pragma unroll
        for (int j = 0; j < 32; j++) qv += Wq[tid * 32 + j] * sz[j];
        g_qs[tid] = qv * C_SCALE;
    }
    if (out_final && tid < 16) {
        if (out_elems == 16) out_final[tid] = sz[2 * tid];           // Re(z)
        else { out_final[2 * tid] = sz[2 * tid]; if (2 * tid + 1 < out_elems) out_final[2 * tid + 1] = sz[2 * tid + 1]; }
    }
}

// ---------------------------------------------------------------------------
// Launch
// ---------------------------------------------------------------------------
extern "C" void kernel_launch(void* const* d_in, const int* in_sizes, int n_in,
                              void* d_out, int out_size)
{
    int idx32[8], n32 = 0;
    int idx1k[8], n1k = 0;
    int idx1[4],  n1  = 0;
    int idxRel = -1, idxCoup = -1, idxBig = -1;
    long long bigSize = 0;
    for (int i = 0; i < n_in; i++) {
        int s = in_sizes[i];
        if (s == 32) { if (n32 < 8) idx32[n32++] = i; }
        else if (s == 1024) { if (n1k < 8) idx1k[n1k++] = i; }
        else if (s == 4128) idxRel = i;
        else if (s == 8) idxCoup = i;
        else if (s == 1) { if (n1 < 4) idx1[n1++] = i; }
        else if ((long long)s > bigSize) { bigSize = s; idxBig = i; }
    }
    if (idxBig < 0 || idxRel < 0 || idxCoup < 0 || n32 < 5 || n1k < 4) return;

    const float *cand, *Wq, *bq, *Wk, *bk, *Wv, *bv, *Wo, *bo;
    bool insertion = idx32[0] < idx1k[0];
    if (insertion) {
        cand = (const float*)d_in[idx32[0]];
        bq   = (const float*)d_in[idx32[1]];
        bk   = (const float*)d_in[idx32[2]];
        bv   = (const float*)d_in[idx32[3]];
        bo   = (const float*)d_in[idx32[4]];
        Wq   = (const float*)d_in[idx1k[0]];
        Wk   = (const float*)d_in[idx1k[1]];
        Wv   = (const float*)d_in[idx1k[2]];
        Wo   = (const float*)d_in[idx1k[3]];
    } else {
        Wk   = (const float*)d_in[idx1k[0]];
        Wo   = (const float*)d_in[idx1k[1]];
        Wq   = (const float*)d_in[idx1k[2]];
        Wv   = (const float*)d_in[idx1k[3]];
        bk   = (const float*)d_in[idx32[0]];
        bo   = (const float*)d_in[idx32[1]];
        bq   = (const float*)d_in[idx32[2]];
        bv   = (const float*)d_in[idx32[3]];
        cand = (const float*)d_in[idx32[4]];
    }
    const float* rel  = (const float*)d_in[idxRel];
    const float* coup = (const float*)d_in[idxCoup];
    const float* nsc  = (n1 > 0) ? (const float*)d_in[idx1[0]] : nullptr;
    const int*   pos  = (n1 > 1) ? (const int*)d_in[idx1[1]] : nullptr;

    int P = in_sizes[idxBig] / 32;
    if (P > P_MAX) P = P_MAX;
    int PAD = (P + 63) & ~63;         // even tile count
    int ntiles = PAD / 32;

    static int smem_set = 0;
    const int PRE_SMEM = 16512 + 32768 + 36864;   // 86144 B
    if (!smem_set) {
        cudaFuncSetAttribute(precompute_kernel,
                             cudaFuncAttributeMaxDynamicSharedMemorySize, PRE_SMEM);
        smem_set = 1;
    }

    precompute_kernel<<<148, 256, PRE_SMEM>>>((const float*)d_in[idxBig],
                                              Wk, bk, Wv, bv, rel, pos, P, ntiles);
    init_kernel<<<1, 32>>>(cand, Wq, bq);

    for (int m = 0; m < M_STEPS; m++) {
        step_kernel<<<NB, 256>>>(ntiles, P, m, Wo, bo, Wq, bq, coup, nsc,
                                 (m == M_STEPS - 1) ? (float*)d_out : nullptr,
                                 out_size);
    }
}